// round 4
// baseline (speedup 1.0000x reference)
#include <cuda_runtime.h>
#include <math.h>

#define NROW 2048
#define HID  64

// ---------------- scratch (device globals) ----------------
__device__ float g_qn[NROW*HID];
__device__ float g_kn[NROW*HID];
__device__ float g_rowsum[NROW];
__device__ float g_colsum[NROW];
__device__ float g_diag[NROW];
__device__ float g_meanpart[256*64];
__device__ float g_timepart[256];
__device__ unsigned int g_tilecnt = 0;
__device__ unsigned int g_cnt = 0;
__device__ unsigned int g_gen = 0;

// Generation-based grid barrier: no reset needed across graph replays.
__device__ __forceinline__ void gsync(int G){
    __threadfence();
    __syncthreads();
    if (threadIdx.x == 0){
        unsigned my = *(volatile unsigned*)&g_gen;
        unsigned old = atomicAdd(&g_cnt, 1u);
        if (old == (unsigned)G - 1u){
            g_cnt = 0;
            __threadfence();
            atomicAdd(&g_gen, 1u);
        } else {
            while (*(volatile unsigned*)&g_gen == my) __nanosleep(64);
        }
    }
    __syncthreads();
    __threadfence();
}

// Fast exp on FMA pipe (cephes exp2f poly); |x| <= ~80.
__device__ __forceinline__ float fexp(float x){
    float y = x * 1.44269504088896341f;
    float n = rintf(y);
    float f = y - n;
    float p = 1.535336188319500e-4f;
    p = fmaf(p, f, 1.339887440266574e-3f);
    p = fmaf(p, f, 9.618437357674640e-3f);
    p = fmaf(p, f, 5.550332471162809e-2f);
    p = fmaf(p, f, 2.402264791363012e-1f);
    p = fmaf(p, f, 6.931472028550421e-1f);
    p = fmaf(p, f, 1.0f);
    int e = (int)n;
    return p * __int_as_float((e + 127) << 23);
}

#define DOT4(acc, w0,w1,w2,w3, v) \
    acc = fmaf(w0,(v).x,fmaf(w1,(v).y,fmaf(w2,(v).z,fmaf(w3,(v).w,acc))));

// smem float offsets (phase A)
#define OW   0        // weights 8192
#define OH   8192     // h halo 15*128
#define OX   10112    // x halo 15*16
#define OZT  10368    // zt 15*64
#define OWH  11392    // wh 15*64
#define OSI  12352    // si 9*32
#define OSJ  12672    // sj 15*32
#define OSDP 13152    // 4*32
#define OBM  13280    // 32
#define OWM2 13312    // 32
#define OU1  13344    // 16
#define OU2  13360    // 16
#define OES  13376    // 80
#define OAT  13456    // 80 (pad to 13568)
#define OCS  13568    // 9*128
#define OZR  14720    // 9*64
#define ONRM 15296    // 36 pad 64
#define ORED 15424    // 256

#define SMEMF 18464   // total floats (72.1KB); logits: qT=0,kT=8192,colPart=16384,tile@18448

__global__ void __launch_bounds__(256, 2)
fused_kernel(const float* __restrict__ h,      const float* __restrict__ x_raw,
             const float* __restrict__ W_in,   const float* __restrict__ b_in,
             const float* __restrict__ dt_emb, const float* __restrict__ Wm1,
             const float* __restrict__ bm1,    const float* __restrict__ Wm2,
             const float* __restrict__ bm2,    const float* __restrict__ Wg,
             const float* __restrict__ a1,     const float* __restrict__ a2,
             const float* __restrict__ Wf,     const float* __restrict__ bf,
             float* __restrict__ out)
{
    extern __shared__ float sm[];

    const int tid  = threadIdx.x;
    const int bid  = blockIdx.x;
    const int G    = gridDim.x;
    const int lane = tid & 31;
    const int wid  = tid >> 5;
    const int c    = tid & 63;
    const int quad = tid >> 6;

    // ================= PHASE A: fused feat+attn, 8 rows per block ==========
    if (bid < 256){
        const int lo = (bid >> 6) << 9;
        const int hi = lo + 511;
        const int i0 = (bid & 63) << 3;
        const int gbase = lo + i0;
        const bool has9 = (i0 + 8) < 512;
        const int NZ = has9 ? 9 : 8;

        // zero this block's rowsum/colsum slices; reset tile counter
        if (tid < 8)       g_rowsum[bid*8 + tid] = 0.f;
        else if (tid < 16) g_colsum[bid*8 + tid - 8] = 0.f;
        if (bid == 0 && tid == 0) g_tilecnt = 0;

        // ---- stage W_in, h halo, x halo, sdp, bm1, Wm2 ----
        {
            const float4* src = (const float4*)W_in;
            float4* dst = (float4*)(sm + OW);
            #pragma unroll
            for (int p = 0; p < 8; p++) dst[tid + p*256] = src[tid + p*256];
        }
        for (int idx = tid; idx < 480; idx += 256){
            int s = idx >> 5, p = idx & 31;
            int j = gbase - 3 + s; j = j < lo ? lo : (j > hi ? hi : j);
            ((float4*)(sm + OH))[idx] = ((const float4*)h)[j*32 + p];
        }
        if (tid < 60){
            int s = tid >> 2, p = tid & 3;
            int j = gbase - 3 + s; j = j < lo ? lo : (j > hi ? hi : j);
            ((float4*)(sm + OX))[tid] = ((const float4*)x_raw)[j*4 + p];
        }
        if (tid < 128){
            int t = tid >> 5, m = tid & 31;
            float s = 0.f;
            #pragma unroll
            for (int e = 0; e < 8; e++)
                s = fmaf(dt_emb[t*8 + e], Wm1[(32 + e)*32 + m], s);
            sm[OSDP + tid] = s;
        } else if (tid < 160) sm[OBM + tid - 128] = bm1[tid - 128];
        else if (tid < 192)   sm[OWM2 + tid - 160] = Wm2[tid - 160];
        const float bm2v = bm2[0];
        __syncthreads();

        // ---- GEMM1: zt = relu(h @ W_in + b_in), 15 rows, K=128 ----
        {
            int r0 = quad*4;
            int r3 = r0 + 3 > 14 ? 14 : r0 + 3;
            float p0=0.f, p1=0.f, p2=0.f, p3=0.f;
            const float4* H4 = (const float4*)(sm + OH);
            #pragma unroll
            for (int kk = 0; kk < 32; kk++){
                int kb = kk*4;
                float w0 = sm[OW + (kb+0)*64 + c];
                float w1 = sm[OW + (kb+1)*64 + c];
                float w2 = sm[OW + (kb+2)*64 + c];
                float w3 = sm[OW + (kb+3)*64 + c];
                float4 v0 = H4[(r0+0)*32 + kk];
                float4 v1 = H4[(r0+1)*32 + kk];
                float4 v2 = H4[(r0+2)*32 + kk];
                float4 v3 = H4[r3*32 + kk];
                DOT4(p0, w0,w1,w2,w3, v0);
                DOT4(p1, w0,w1,w2,w3, v1);
                DOT4(p2, w0,w1,w2,w3, v2);
                DOT4(p3, w0,w1,w2,w3, v3);
            }
            float bi = b_in[c];
            sm[OZT + (r0+0)*64 + c] = fmaxf(p0 + bi, 0.f);
            sm[OZT + (r0+1)*64 + c] = fmaxf(p1 + bi, 0.f);
            sm[OZT + (r0+2)*64 + c] = fmaxf(p2 + bi, 0.f);
            if (r0 + 3 < 15) sm[OZT + (r0+3)*64 + c] = fmaxf(p3 + bi, 0.f);
        }
        // ---- si (9 rows), sj (15 rows) ----
        for (int idx = tid; idx < 768; idx += 256){
            int rr = idx >> 5, m = idx & 31;
            float s = 0.f;
            if (rr < 9){
                const float* xp = sm + OX + (rr+3)*16;
                #pragma unroll
                for (int q2 = 0; q2 < 16; q2++) s = fmaf(xp[q2], Wm1[q2*32 + m], s);
                sm[OSI + rr*32 + m] = s;
            } else {
                const float* xp = sm + OX + (rr-9)*16;
                #pragma unroll
                for (int q2 = 0; q2 < 16; q2++) s = fmaf(xp[q2], Wm1[(16+q2)*32 + m], s);
                sm[OSJ + (rr-9)*32 + m] = s;
            }
        }
        __syncthreads();

        // ---- stage Wg ----
        {
            const float4* src = (const float4*)Wg;
            float4* dst = (float4*)(sm + OW);
            #pragma unroll
            for (int p = 0; p < 4; p++) dst[tid + p*256] = src[tid + p*256];
        }
        __syncthreads();

        // ---- GEMM2: wh = zt @ Wg, 15 rows, K=64 ----
        {
            int r0 = quad*4;
            int r3 = r0 + 3 > 14 ? 14 : r0 + 3;
            float p0=0.f, p1=0.f, p2=0.f, p3=0.f;
            const float4* Z4 = (const float4*)(sm + OZT);
            #pragma unroll
            for (int kk = 0; kk < 16; kk++){
                int kb = kk*4;
                float w0 = sm[OW + (kb+0)*64 + c];
                float w1 = sm[OW + (kb+1)*64 + c];
                float w2 = sm[OW + (kb+2)*64 + c];
                float w3 = sm[OW + (kb+3)*64 + c];
                float4 v0 = Z4[(r0+0)*16 + kk];
                float4 v1 = Z4[(r0+1)*16 + kk];
                float4 v2 = Z4[(r0+2)*16 + kk];
                float4 v3 = Z4[r3*16 + kk];
                DOT4(p0, w0,w1,w2,w3, v0);
                DOT4(p1, w0,w1,w2,w3, v1);
                DOT4(p2, w0,w1,w2,w3, v2);
                DOT4(p3, w0,w1,w2,w3, v3);
            }
            sm[OWH + (r0+0)*64 + c] = p0;
            sm[OWH + (r0+1)*64 + c] = p1;
            sm[OWH + (r0+2)*64 + c] = p2;
            if (r0 + 3 < 15) sm[OWH + (r0+3)*64 + c] = p3;
        }
        __syncthreads();

        // ---- stage Wf + u-dots ----
        {
            const float4* src = (const float4*)Wf;
            float4* dst = (float4*)(sm + OW);
            #pragma unroll
            for (int p = 0; p < 8; p++) dst[tid + p*256] = src[tid + p*256];
        }
        for (int t = wid; t < 24; t += 8){
            const float* whp; const float* av;
            if (t < 9){ whp = sm + OWH + (t+3)*64; av = a1; }
            else      { whp = sm + OWH + (t-9)*64; av = a2; }
            float v = whp[lane]*av[lane] + whp[lane+32]*av[lane+32];
            #pragma unroll
            for (int s = 16; s > 0; s >>= 1) v += __shfl_down_sync(0xffffffffu, v, s);
            if (lane == 0){
                if (t < 9) sm[OU1 + t] = v; else sm[OU2 + t - 9] = v;
            }
        }
        __syncthreads();

        // ---- bias: NZ*7 warp-tasks ----
        for (int t = wid; t < NZ*7; t += 8){
            int r = t / 7, o = t - r*7;
            int i = i0 + r, j = i - 3 + o, jj = r + o;
            int dtv = 3 - o; if (dtv < 0) dtv = 0;
            float v = sm[OSI + r*32 + lane] + sm[OSJ + jj*32 + lane]
                    + sm[OSDP + dtv*32 + lane] + sm[OBM + lane];
            float p = v > 0.f ? v * sm[OWM2 + lane] : 0.f;
            #pragma unroll
            for (int s = 16; s > 0; s >>= 1) p += __shfl_down_sync(0xffffffffu, p, s);
            if (lane == 0){
                float e = -1e30f;
                if (j >= 0 && j < 512){
                    float u = sm[OU1 + r] + sm[OU2 + jj];
                    float lr = u > 0.f ? u : 0.2f*u;
                    e = lr + p + bm2v - 0.2f*(float)dtv;
                }
                sm[OES + r*8 + o] = e;
            }
        }
        __syncthreads();
        if (tid < NZ){
            float mx = -1e30f;
            #pragma unroll
            for (int o = 0; o < 7; o++) mx = fmaxf(mx, sm[OES + tid*8 + o]);
            float sum = 0.f, ex[7];
            #pragma unroll
            for (int o = 0; o < 7; o++){
                float e = sm[OES + tid*8 + o];
                ex[o] = e > -1e29f ? fexp(e - mx) : 0.f;
                sum += ex[o];
            }
            float inv = 1.f / sum;
            #pragma unroll
            for (int o = 0; o < 7; o++) sm[OAT + tid*8 + o] = ex[o]*inv;
        }
        __syncthreads();

        // ---- zg = elu(attn @ wh); build cs = [zt|zg] ----
        for (int r = quad; r < NZ; r += 4){
            float acc = 0.f;
            #pragma unroll
            for (int o = 0; o < 7; o++)
                acc = fmaf(sm[OAT + r*8 + o], sm[OWH + (r+o)*64 + c], acc);
            float zg = acc > 0.f ? acc : expm1f(acc);
            sm[OCS + r*128 + 64 + c] = zg;
            sm[OCS + r*128 + c]      = sm[OZT + (r+3)*64 + c];
        }
        __syncthreads();

        // ---- GEMM3: z = relu(cs @ Wf + bf), NZ rows, K=128 ----
        {
            int r0 = quad*4;
            int ra = r0   < NZ ? r0   : NZ-1;
            int rb = r0+1 < NZ ? r0+1 : NZ-1;
            int rc = r0+2 < NZ ? r0+2 : NZ-1;
            int rd = r0+3 < NZ ? r0+3 : NZ-1;
            float p0=0.f, p1=0.f, p2=0.f, p3=0.f;
            const float4* C4 = (const float4*)(sm + OCS);
            #pragma unroll
            for (int kk = 0; kk < 32; kk++){
                int kb = kk*4;
                float w0 = sm[OW + (kb+0)*64 + c];
                float w1 = sm[OW + (kb+1)*64 + c];
                float w2 = sm[OW + (kb+2)*64 + c];
                float w3 = sm[OW + (kb+3)*64 + c];
                float4 v0 = C4[ra*32 + kk];
                float4 v1 = C4[rb*32 + kk];
                float4 v2 = C4[rc*32 + kk];
                float4 v3 = C4[rd*32 + kk];
                DOT4(p0, w0,w1,w2,w3, v0);
                DOT4(p1, w0,w1,w2,w3, v1);
                DOT4(p2, w0,w1,w2,w3, v2);
                DOT4(p3, w0,w1,w2,w3, v3);
            }
            float bfc = bf[c];
            if (r0   < NZ) sm[OZR + (r0  )*64 + c] = fmaxf(p0 + bfc, 0.f);
            if (r0+1 < NZ) sm[OZR + (r0+1)*64 + c] = fmaxf(p1 + bfc, 0.f);
            if (r0+2 < NZ) sm[OZR + (r0+2)*64 + c] = fmaxf(p2 + bfc, 0.f);
            if (r0+3 < NZ) sm[OZR + (r0+3)*64 + c] = fmaxf(p3 + bfc, 0.f);
        }
        __syncthreads();

        // ---- norms: 4*NZ warp-tasks ----
        for (int t = wid; t < 4*NZ; t += 8){
            int r = t >> 2, which = t & 3;
            float v;
            if (which == 0){
                float x1 = sm[OZR + r*64 + lane], x2 = sm[OZR + r*64 + lane + 32];
                v = x1*x1 + x2*x2;
            } else if (which == 1){
                float x1 = sm[OZT + (r+3)*64 + lane], x2 = sm[OZT + (r+3)*64 + lane + 32];
                v = x1*x1 + x2*x2;
            } else if (which == 2){
                float x1 = sm[OCS + r*128 + 64 + lane], x2 = sm[OCS + r*128 + 96 + lane];
                v = x1*x1 + x2*x2;
            } else {
                v = sm[OZT + (r+3)*64 + lane]      * sm[OCS + r*128 + 64 + lane]
                  + sm[OZT + (r+3)*64 + lane + 32] * sm[OCS + r*128 + 96 + lane];
            }
            #pragma unroll
            for (int s = 16; s > 0; s >>= 1) v += __shfl_down_sync(0xffffffffu, v, s);
            if (lane == 0) sm[ONRM + r*4 + which] = v;
        }
        __syncthreads();

        // ---- outputs: qn, kn, diag (8 main rows) ----
        for (int r = quad; r < 8; r += 4){
            float invzt = 1.f / fmaxf(sqrtf(sm[ONRM + r*4 + 1]), 1e-8f);
            float invzg = 1.f / fmaxf(sqrtf(sm[ONRM + r*4 + 2]), 1e-8f);
            int gr = gbase + r;
            g_qn[gr*64 + c] = sm[OZT + (r+3)*64 + c] * invzt;
            g_kn[gr*64 + c] = sm[OCS + r*128 + 64 + c] * invzg;
            if (c == 0) g_diag[gr] = 10.f * sm[ONRM + r*4 + 3] * invzt * invzg;
        }
        // ---- mean partial ----
        if (tid < 64){
            float ms = 0.f;
            #pragma unroll
            for (int r = 0; r < 8; r++){
                float invz = 1.f / fmaxf(sqrtf(sm[ONRM + r*4]), 1e-8f);
                ms += sm[OZR + r*64 + tid] * invz;
            }
            g_meanpart[bid*64 + tid] = ms;
        }
        // ---- time partial: pairs (r, r+1), r = wid ----
        {
            int r = wid;
            float contrib = 0.f;
            if (r < 7 || has9){
                float iz1 = 1.f / fmaxf(sqrtf(sm[ONRM + r*4]), 1e-8f);
                float iz2 = 1.f / fmaxf(sqrtf(sm[ONRM + (r+1)*4]), 1e-8f);
                float d = sm[OZR + r*64 + lane]      * sm[OZR + (r+1)*64 + lane]
                        + sm[OZR + r*64 + lane + 32] * sm[OZR + (r+1)*64 + lane + 32];
                #pragma unroll
                for (int s = 16; s > 0; s >>= 1) d += __shfl_down_sync(0xffffffffu, d, s);
                if (lane == 0){
                    float cosv = d * iz1 * iz2;
                    float dd = 1.f - cosv;
                    contrib = dd*dd;
                }
            }
            if (lane == 0) sm[ORED + wid] = contrib;
        }
        __syncthreads();
        if (tid == 0){
            float ts = 0.f;
            #pragma unroll
            for (int w = 0; w < 8; w++) ts += sm[ORED + w];
            g_timepart[bid] = ts;
        }
    }

    gsync(G);

    // ================= PHASE B: logits 128x128 tiles, work-stealing ========
    {
        float* qT = sm;                 // [64][128]
        float* kT = sm + 8192;          // [64][128]
        float* colPart = sm + 16384;    // [16][128]
        int* tslot = (int*)(sm + 18448);
        const int tx = tid & 15, ty = tid >> 4;

        while (true){
            __syncthreads();
            if (tid == 0) *tslot = (int)atomicAdd(&g_tilecnt, 1u);
            __syncthreads();
            int tI = *tslot;
            if (tI >= 256) break;
            int rb2 = (tI & 15) << 7, cb2 = (tI >> 4) << 7;

            for (int idx = tid; idx < 2048; idx += 256){
                int i = idx & 127, kg = idx >> 7;
                float4 q4 = *(const float4*)&g_qn[(rb2+i)*64 + kg*4];
                float4 k4 = *(const float4*)&g_kn[(cb2+i)*64 + kg*4];
                qT[(kg*4+0)*128 + i] = q4.x;
                qT[(kg*4+1)*128 + i] = q4.y;
                qT[(kg*4+2)*128 + i] = q4.z;
                qT[(kg*4+3)*128 + i] = q4.w;
                kT[(kg*4+0)*128 + i] = k4.x;
                kT[(kg*4+1)*128 + i] = k4.y;
                kT[(kg*4+2)*128 + i] = k4.z;
                kT[(kg*4+3)*128 + i] = k4.w;
            }
            __syncthreads();

            float acc[8][8];
            #pragma unroll
            for (int a = 0; a < 8; a++)
                #pragma unroll
                for (int b = 0; b < 8; b++) acc[a][b] = 0.f;

            #pragma unroll 2
            for (int k = 0; k < 64; k++){
                float4 a0 = *(const float4*)&qT[k*128 + ty*4];
                float4 a1v = *(const float4*)&qT[k*128 + 64 + ty*4];
                float4 b0 = *(const float4*)&kT[k*128 + tx*4];
                float4 b1 = *(const float4*)&kT[k*128 + 64 + tx*4];
                float av[8] = {a0.x,a0.y,a0.z,a0.w, a1v.x,a1v.y,a1v.z,a1v.w};
                float bv[8] = {b0.x,b0.y,b0.z,b0.w, b1.x,b1.y,b1.z,b1.w};
                #pragma unroll
                for (int a = 0; a < 8; a++)
                    #pragma unroll
                    for (int b = 0; b < 8; b++)
                        acc[a][b] = fmaf(av[a], bv[b], acc[a][b]);
            }

            float rs[8] = {0,0,0,0,0,0,0,0};
            float cs[8] = {0,0,0,0,0,0,0,0};
            #pragma unroll
            for (int a = 0; a < 8; a++)
                #pragma unroll
                for (int b = 0; b < 8; b++){
                    float p = fexp(acc[a][b] * 10.f);
                    rs[a] += p; cs[b] += p;
                }

            #pragma unroll
            for (int a = 0; a < 8; a++){
                #pragma unroll
                for (int o = 8; o > 0; o >>= 1)
                    rs[a] += __shfl_xor_sync(0xffffffffu, rs[a], o);
            }
            if (tx == 0){
                #pragma unroll
                for (int a = 0; a < 8; a++){
                    int row = (a < 4) ? (ty*4 + a) : (64 + ty*4 + a - 4);
                    atomicAdd(&g_rowsum[rb2 + row], rs[a]);
                }
            }
            #pragma unroll
            for (int b = 0; b < 4; b++){
                colPart[ty*128 + tx*4 + b]      = cs[b];
                colPart[ty*128 + 64 + tx*4 + b] = cs[b+4];
            }
            __syncthreads();
            if (tid < 128){
                float s = 0.f;
                #pragma unroll
                for (int t = 0; t < 16; t++) s += colPart[t*128 + tid];
                atomicAdd(&g_colsum[cb2 + tid], s);
            }
        }
    }

    gsync(G);

    // ================= PHASE C: final combine (block 0) =================
    if (bid == 0){
        float ms = 0.f;
        for (int blk = quad; blk < 256; blk += 4)
            ms += __ldcg(&g_meanpart[blk*64 + c]);
        sm[tid] = ms;
        __syncthreads();
        if (tid < 64){
            float Mv = sm[tid] + sm[64+tid] + sm[128+tid] + sm[192+tid];
            sm[256 + tid] = Mv*Mv;
        }
        __syncthreads();

        float tv = __ldcg(&g_timepart[tid]);
        float s = 0.f;
        for (int r = tid; r < 2048; r += 256)
            s += logf(__ldcg(&g_rowsum[r])) + logf(__ldcg(&g_colsum[r]))
               - 2.f*__ldcg(&g_diag[r]);
        sm[512 + tid] = tv;
        sm[768 + tid] = s;
        __syncthreads();
        for (int st = 128; st > 0; st >>= 1){
            if (tid < st){
                sm[512+tid] += sm[512+tid+st];
                sm[768+tid] += sm[768+tid+st];
            }
            __syncthreads();
        }
        if (tid == 0){
            float nm2 = 0.f;
            #pragma unroll
            for (int i = 0; i < 64; i++) nm2 += sm[256 + i];
            float normM = sqrtf(nm2);
            float l_con = 0.5f * sm[768] / 2048.f;
            float l_sc  = -normM / 2048.f;
            float l_t   =  sm[512] / 2044.f;
            out[0] = l_con + l_sc + l_t;
            out[1] = l_con;
            out[2] = l_sc;
            out[3] = l_t;
        }
    }
}

// ---------------- launch ----------------
extern "C" void kernel_launch(void* const* d_in, const int* in_sizes, int n_in,
                              void* d_out, int out_size){
    const float* h      = (const float*)d_in[0];
    const float* x_raw  = (const float*)d_in[1];
    const float* W_in   = (const float*)d_in[2];
    const float* b_in   = (const float*)d_in[3];
    const float* dt_emb = (const float*)d_in[4];
    const float* Wm1    = (const float*)d_in[5];
    const float* bm1    = (const float*)d_in[6];
    const float* Wm2    = (const float*)d_in[7];
    const float* bm2    = (const float*)d_in[8];
    const float* Wg     = (const float*)d_in[9];
    const float* a1     = (const float*)d_in[10];
    const float* a2     = (const float*)d_in[11];
    const float* Wf     = (const float*)d_in[12];
    const float* bf     = (const float*)d_in[13];
    float* out = (float*)d_out;

    const int SMEM = SMEMF * 4;
    cudaFuncSetAttribute(fused_kernel, cudaFuncAttributeMaxDynamicSharedMemorySize, SMEM);

    int dev = 0; cudaGetDevice(&dev);
    int sms = 0;
    cudaDeviceGetAttribute(&sms, cudaDevAttrMultiProcessorCount, dev);
    if (sms <= 0) sms = 148;
    int G = sms * 2;
    if (G < 257) G = 257;   // need blocks 0..255 in phase A

    fused_kernel<<<G, 256, SMEM>>>(h, x_raw, W_in, b_in, dt_emb, Wm1, bm1, Wm2, bm2,
                                   Wg, a1, a2, Wf, bf, out);
}

// round 5
// speedup vs baseline: 1.1193x; 1.1193x over previous
#include <cuda_runtime.h>
#include <math.h>

// ---- smem float offsets (phase A) ----
#define OH    0       // h stage 8*128
#define OX    1024    // x stage 8*16
#define OZT   1152    // zt 8*64
#define OWH   1664    // wh 8*64
#define OC    2304    // gemm partials 4*8*64
#define OSI   4352    // si 8*32
#define OSJ   4608    // sj halo 14*32
#define OWHH  5056    // wh halo 14*64
#define OU1   5952    // 8
#define OU2   5960    // 14
#define OSDP  5984    // 4*32
#define OBM   6112    // 32
#define OWM2  6144    // 32
#define OES   6176    // 64
#define OAT   6240    // 64
#define OCS   6304    // cs 8*128
#define OZR   7328    // z 8*64
#define ONRM  7840    // 32
#define ORED  7872    // 8
#define SMEMF 18432   // logits: qT=0(8192), kT=8192(8192), colPart=16384(2048)

// ---------------- scratch (device globals) ----------------
__device__ float g_sj[2048*32];
__device__ float g_wh[2048*64];
__device__ float g_u2[2048];
__device__ float g_qn[2048*64];
__device__ float g_kn[2048*64];
__device__ float g_rowsum[2048];
__device__ float g_colsum[2048];
__device__ float g_diag[2048];
__device__ float g_meanpart[256*64];
__device__ float g_timepart[256];
__device__ float g_znfirst[256*64];
__device__ float g_znlast[256*64];
__device__ unsigned int g_cnt = 0;
__device__ unsigned int g_gen = 0;

// Generation-based grid barrier: no reset needed across graph replays.
__device__ __forceinline__ void gsync(int G){
    __threadfence();
    __syncthreads();
    if (threadIdx.x == 0){
        unsigned my = *(volatile unsigned*)&g_gen;
        unsigned old = atomicAdd(&g_cnt, 1u);
        if (old == (unsigned)G - 1u){
            g_cnt = 0;
            __threadfence();
            atomicAdd(&g_gen, 1u);
        } else {
            while (*(volatile unsigned*)&g_gen == my) __nanosleep(64);
        }
    }
    __syncthreads();
    __threadfence();
}

// Fast exp on FMA pipe (cephes exp2f poly); |x| <= ~80.
__device__ __forceinline__ float fexp(float x){
    float y = x * 1.44269504088896341f;
    float n = rintf(y);
    float f = y - n;
    float p = 1.535336188319500e-4f;
    p = fmaf(p, f, 1.339887440266574e-3f);
    p = fmaf(p, f, 9.618437357674640e-3f);
    p = fmaf(p, f, 5.550332471162809e-2f);
    p = fmaf(p, f, 2.402264791363012e-1f);
    p = fmaf(p, f, 6.931472028550421e-1f);
    p = fmaf(p, f, 1.0f);
    int e = (int)n;
    return p * __int_as_float((e + 127) << 23);
}

__global__ void __launch_bounds__(256, 2)
fused_kernel(const float* __restrict__ h,      const float* __restrict__ x_raw,
             const float* __restrict__ W_in,   const float* __restrict__ b_in,
             const float* __restrict__ dt_emb, const float* __restrict__ Wm1,
             const float* __restrict__ bm1,    const float* __restrict__ Wm2,
             const float* __restrict__ bm2,    const float* __restrict__ Wg,
             const float* __restrict__ a1,     const float* __restrict__ a2,
             const float* __restrict__ Wf,     const float* __restrict__ bf,
             float* __restrict__ out)
{
    extern __shared__ float sm[];

    const int tid  = threadIdx.x;
    const int bid  = blockIdx.x;
    const int G    = gridDim.x;
    const int lane = tid & 31;
    const int wid  = tid >> 5;
    const int c    = tid & 63;
    const int quad = tid >> 6;       // 0..3: k-quarter
    const int rp   = tid >> 6;       // rows rp, rp+4 for 2-row/thread steps

    // ================= PHASE 0: features, 8 rows per block =================
    if (bid < 256){
        const int gbase = bid*8;
        const int lo = gbase & ~511, hi = lo + 511;

        if (tid < 8)       g_rowsum[gbase + tid] = 0.f;
        else if (tid < 16) g_colsum[gbase + tid - 8] = 0.f;

        // stage h (8x128) and x (8x16); phase-1 constants
        {
            int row = tid >> 5, p = tid & 31;
            ((float4*)(sm + OH))[tid] = ((const float4*)h)[(gbase+row)*32 + p];
        }
        if (tid < 32){
            int row = tid >> 2, p = tid & 3;
            ((float4*)(sm + OX))[tid] = ((const float4*)x_raw)[(gbase+row)*4 + p];
        }
        if (tid >= 64 && tid < 192){
            int t = (tid - 64) >> 5, m = tid & 31;
            float s = 0.f;
            #pragma unroll
            for (int e = 0; e < 8; e++)
                s = fmaf(dt_emb[t*8 + e], Wm1[(32 + e)*32 + m], s);
            sm[OSDP + (tid - 64)] = s;
        } else if (tid >= 192 && tid < 224) sm[OBM  + tid - 192] = bm1[tid - 192];
        else if (tid >= 224)                sm[OWM2 + tid - 224] = Wm2[tid - 224];
        __syncthreads();

        // GEMM1 partials: zt_pre = h @ W_in ; thread (c, quad): 8 rows, 32 k's
        {
            float acc[8] = {0,0,0,0,0,0,0,0};
            const float4* H4 = (const float4*)(sm + OH);
            #pragma unroll
            for (int kk = 0; kk < 8; kk++){
                int kb = quad*32 + kk*4;
                float w0 = W_in[(kb+0)*64 + c];
                float w1 = W_in[(kb+1)*64 + c];
                float w2 = W_in[(kb+2)*64 + c];
                float w3 = W_in[(kb+3)*64 + c];
                #pragma unroll
                for (int r = 0; r < 8; r++){
                    float4 v = H4[r*32 + (kb>>2)];
                    acc[r] = fmaf(w0, v.x, fmaf(w1, v.y, fmaf(w2, v.z, fmaf(w3, v.w, acc[r]))));
                }
            }
            #pragma unroll
            for (int r = 0; r < 8; r++) sm[OC + quad*512 + r*64 + c] = acc[r];
        }
        // si (smem only) / sj (global): warp w -> row w, lane -> m
        {
            const float* xp = sm + OX + wid*16;
            float si = 0.f, sj = 0.f;
            #pragma unroll
            for (int q = 0; q < 16; q++){
                float xv = xp[q];
                si = fmaf(xv, Wm1[q*32 + lane], si);
                sj = fmaf(xv, Wm1[(16+q)*32 + lane], sj);
            }
            sm[OSI + wid*32 + lane] = si;
            g_sj[(gbase + wid)*32 + lane] = sj;
        }
        __syncthreads();

        // combine zt
        {
            float bi = b_in[c];
            #pragma unroll
            for (int s = 0; s < 2; s++){
                int rr = rp + s*4;
                float z = bi + sm[OC + 0*512 + rr*64 + c] + sm[OC + 1*512 + rr*64 + c]
                             + sm[OC + 2*512 + rr*64 + c] + sm[OC + 3*512 + rr*64 + c];
                sm[OZT + rr*64 + c] = fmaxf(z, 0.f);
            }
        }
        __syncthreads();

        // GEMM2 partials: wh = zt @ Wg ; K=64, thread (c, quad): 16 k's
        {
            float acc[8] = {0,0,0,0,0,0,0,0};
            const float4* Z4 = (const float4*)(sm + OZT);
            #pragma unroll
            for (int kk = 0; kk < 4; kk++){
                int kb = quad*16 + kk*4;
                float w0 = Wg[(kb+0)*64 + c];
                float w1 = Wg[(kb+1)*64 + c];
                float w2 = Wg[(kb+2)*64 + c];
                float w3 = Wg[(kb+3)*64 + c];
                #pragma unroll
                for (int r = 0; r < 8; r++){
                    float4 v = Z4[r*16 + (kb>>2)];
                    acc[r] = fmaf(w0, v.x, fmaf(w1, v.y, fmaf(w2, v.z, fmaf(w3, v.w, acc[r]))));
                }
            }
            #pragma unroll
            for (int r = 0; r < 8; r++) sm[OC + quad*512 + r*64 + c] = acc[r];
        }
        __syncthreads();
        {
            #pragma unroll
            for (int s = 0; s < 2; s++){
                int rr = rp + s*4;
                float whv = sm[OC + 0*512 + rr*64 + c] + sm[OC + 1*512 + rr*64 + c]
                          + sm[OC + 2*512 + rr*64 + c] + sm[OC + 3*512 + rr*64 + c];
                sm[OWH + rr*64 + c] = whv;
                g_wh[(gbase + rr)*64 + c] = whv;
            }
        }
        __syncthreads();

        // u1 (smem) / u2 (global): warp w -> row w
        {
            const float* whp = sm + OWH + wid*64;
            float v1 = whp[lane]*a1[lane] + whp[lane+32]*a1[lane+32];
            float v2 = whp[lane]*a2[lane] + whp[lane+32]*a2[lane+32];
            #pragma unroll
            for (int s = 16; s > 0; s >>= 1){
                v1 += __shfl_down_sync(0xffffffffu, v1, s);
                v2 += __shfl_down_sync(0xffffffffu, v2, s);
            }
            if (lane == 0){
                sm[OU1 + wid] = v1;
                g_u2[gbase + wid] = v2;
            }
        }
    }

    gsync(G);

    // ================= PHASE 1: attention + head, 8 rows per block =========
    if (bid < 256){
        const int gbase = bid*8;
        const int lo = gbase & ~511, hi = lo + 511;
        const int i0 = gbase & 511;
        const float bm2v = bm2[0];

        // stage halos
        for (int idx = tid; idx < 448; idx += 256){
            int rr = idx >> 5, m = idx & 31;
            int j = gbase - 3 + rr; j = j < lo ? lo : (j > hi ? hi : j);
            sm[OSJ + idx] = g_sj[j*32 + m];
        }
        for (int idx = tid; idx < 896; idx += 256){
            int rr = idx >> 6, cc = idx & 63;
            int j = gbase - 3 + rr; j = j < lo ? lo : (j > hi ? hi : j);
            sm[OWHH + idx] = g_wh[j*64 + cc];
        }
        if (tid < 14){
            int j = gbase - 3 + tid; j = j < lo ? lo : (j > hi ? hi : j);
            sm[OU2 + tid] = g_u2[j];
        }
        __syncthreads();

        // bias: 56 warp-tasks
        for (int t = wid; t < 56; t += 8){
            int r = t / 7, o = t - r*7;
            int jl = i0 + r - 3 + o;
            int jj = r + o;
            int dtv = 3 - o; if (dtv < 0) dtv = 0;
            float v = sm[OSI + r*32 + lane] + sm[OSJ + jj*32 + lane]
                    + sm[OSDP + dtv*32 + lane] + sm[OBM + lane];
            float p = v > 0.f ? v * sm[OWM2 + lane] : 0.f;
            #pragma unroll
            for (int s = 16; s > 0; s >>= 1) p += __shfl_down_sync(0xffffffffu, p, s);
            if (lane == 0){
                float e = -1e30f;
                if (jl >= 0 && jl < 512){
                    float u = sm[OU1 + r] + sm[OU2 + jj];
                    float lr = u > 0.f ? u : 0.2f*u;
                    e = lr + p + bm2v - 0.2f*(float)dtv;
                }
                sm[OES + r*8 + o] = e;
            }
        }
        __syncthreads();
        if (tid < 8){
            float mx = -1e30f;
            #pragma unroll
            for (int o = 0; o < 7; o++) mx = fmaxf(mx, sm[OES + tid*8 + o]);
            float sum = 0.f, ex[7];
            #pragma unroll
            for (int o = 0; o < 7; o++){
                float e = sm[OES + tid*8 + o];
                ex[o] = e > -1e29f ? fexp(e - mx) : 0.f;
                sum += ex[o];
            }
            float inv = 1.f / sum;
            #pragma unroll
            for (int o = 0; o < 7; o++) sm[OAT + tid*8 + o] = ex[o]*inv;
        }
        __syncthreads();

        // zg = elu(attn @ wh); cs = [zt | zg]
        {
            #pragma unroll
            for (int s = 0; s < 2; s++){
                int rr = rp + s*4;
                float acc = 0.f;
                #pragma unroll
                for (int o = 0; o < 7; o++)
                    acc = fmaf(sm[OAT + rr*8 + o], sm[OWHH + (rr+o)*64 + c], acc);
                float zg = acc > 0.f ? acc : fexp(acc) - 1.f;
                sm[OCS + rr*128 + 64 + c] = zg;
                sm[OCS + rr*128 + c]      = sm[OZT + rr*64 + c];
            }
        }
        __syncthreads();

        // GEMM3 partials: z = cs @ Wf ; K=128
        {
            float acc[8] = {0,0,0,0,0,0,0,0};
            const float4* C4 = (const float4*)(sm + OCS);
            #pragma unroll
            for (int kk = 0; kk < 8; kk++){
                int kb = quad*32 + kk*4;
                float w0 = Wf[(kb+0)*64 + c];
                float w1 = Wf[(kb+1)*64 + c];
                float w2 = Wf[(kb+2)*64 + c];
                float w3 = Wf[(kb+3)*64 + c];
                #pragma unroll
                for (int r = 0; r < 8; r++){
                    float4 v = C4[r*32 + (kb>>2)];
                    acc[r] = fmaf(w0, v.x, fmaf(w1, v.y, fmaf(w2, v.z, fmaf(w3, v.w, acc[r]))));
                }
            }
            #pragma unroll
            for (int r = 0; r < 8; r++) sm[OC + quad*512 + r*64 + c] = acc[r];
        }
        __syncthreads();
        {
            float bfc = bf[c];
            #pragma unroll
            for (int s = 0; s < 2; s++){
                int rr = rp + s*4;
                float z = bfc + sm[OC + 0*512 + rr*64 + c] + sm[OC + 1*512 + rr*64 + c]
                              + sm[OC + 2*512 + rr*64 + c] + sm[OC + 3*512 + rr*64 + c];
                sm[OZR + rr*64 + c] = fmaxf(z, 0.f);
            }
        }
        __syncthreads();

        // norms: 32 warp-tasks (8 rows x {z, zt, zg, zt.zg})
        for (int t = wid; t < 32; t += 8){
            int r = t >> 2, which = t & 3;
            float v;
            if (which == 0){
                float x1 = sm[OZR + r*64 + lane], x2 = sm[OZR + r*64 + lane + 32];
                v = x1*x1 + x2*x2;
            } else if (which == 1){
                float x1 = sm[OZT + r*64 + lane], x2 = sm[OZT + r*64 + lane + 32];
                v = x1*x1 + x2*x2;
            } else if (which == 2){
                float x1 = sm[OCS + r*128 + 64 + lane], x2 = sm[OCS + r*128 + 96 + lane];
                v = x1*x1 + x2*x2;
            } else {
                v = sm[OZT + r*64 + lane]      * sm[OCS + r*128 + 64 + lane]
                  + sm[OZT + r*64 + lane + 32] * sm[OCS + r*128 + 96 + lane];
            }
            #pragma unroll
            for (int s = 16; s > 0; s >>= 1) v += __shfl_down_sync(0xffffffffu, v, s);
            if (lane == 0) sm[ONRM + r*4 + which] = v;
        }
        __syncthreads();

        // outputs: qn, kn, diag
        {
            #pragma unroll
            for (int s = 0; s < 2; s++){
                int rr = rp + s*4;
                float invzt = 1.f / fmaxf(sqrtf(sm[ONRM + rr*4 + 1]), 1e-8f);
                float invzg = 1.f / fmaxf(sqrtf(sm[ONRM + rr*4 + 2]), 1e-8f);
                int gr = gbase + rr;
                g_qn[gr*64 + c] = sm[OZT + rr*64 + c] * invzt;
                g_kn[gr*64 + c] = sm[OCS + rr*128 + 64 + c] * invzg;
                if (c == 0) g_diag[gr] = 10.f * sm[ONRM + rr*4 + 3] * invzt * invzg;
            }
        }
        // mean partial + boundary znorm rows
        if (tid < 64){
            float ms = 0.f;
            float zn0 = 0.f, zn7 = 0.f;
            #pragma unroll
            for (int r = 0; r < 8; r++){
                float invz = 1.f / fmaxf(sqrtf(sm[ONRM + r*4]), 1e-8f);
                float zn = sm[OZR + r*64 + tid] * invz;
                ms += zn;
                if (r == 0) zn0 = zn;
                if (r == 7) zn7 = zn;
            }
            g_meanpart[bid*64 + tid] = ms;
            g_znfirst[bid*64 + tid]  = zn0;
            g_znlast[bid*64 + tid]   = zn7;
        }
        // time local pairs (7)
        if (wid < 7){
            int r = wid;
            float iz1 = 1.f / fmaxf(sqrtf(sm[ONRM + r*4]), 1e-8f);
            float iz2 = 1.f / fmaxf(sqrtf(sm[ONRM + (r+1)*4]), 1e-8f);
            float d = sm[OZR + r*64 + lane]      * sm[OZR + (r+1)*64 + lane]
                    + sm[OZR + r*64 + lane + 32] * sm[OZR + (r+1)*64 + lane + 32];
            #pragma unroll
            for (int s = 16; s > 0; s >>= 1) d += __shfl_down_sync(0xffffffffu, d, s);
            if (lane == 0){
                float dd = 1.f - d*iz1*iz2;
                sm[ORED + r] = dd*dd;
            }
        }
        __syncthreads();
        if (tid == 0){
            float ts = 0.f;
            #pragma unroll
            for (int r = 0; r < 7; r++) ts += sm[ORED + r];
            g_timepart[bid] = ts;
        }
    }

    gsync(G);

    // ================= PHASE B: cross time-pairs + logits ==================
    if (bid < 256){
        // cross pair (gbase+7, gbase+8) unless sequence boundary
        if ((bid & 63) != 63 && wid == 0){
            float d = g_znlast[bid*64 + lane]      * g_znfirst[(bid+1)*64 + lane]
                    + g_znlast[bid*64 + lane + 32] * g_znfirst[(bid+1)*64 + lane + 32];
            #pragma unroll
            for (int s = 16; s > 0; s >>= 1) d += __shfl_down_sync(0xffffffffu, d, s);
            if (lane == 0){
                float dd = 1.f - d;
                g_timepart[bid] += dd*dd;
            }
        }

        // logits tile (static): 128x128, 8x8 micro
        float* qT = sm;
        float* kT = sm + 8192;
        float* colPart = sm + 16384;
        const int tx = tid & 15, ty = tid >> 4;
        const int rb2 = (bid & 15) << 7, cb2 = (bid >> 4) << 7;

        for (int idx = tid; idx < 2048; idx += 256){
            int i = idx & 127, kg = idx >> 7;
            float4 q4 = *(const float4*)&g_qn[(rb2+i)*64 + kg*4];
            float4 k4 = *(const float4*)&g_kn[(cb2+i)*64 + kg*4];
            qT[(kg*4+0)*128 + i] = q4.x;
            qT[(kg*4+1)*128 + i] = q4.y;
            qT[(kg*4+2)*128 + i] = q4.z;
            qT[(kg*4+3)*128 + i] = q4.w;
            kT[(kg*4+0)*128 + i] = k4.x;
            kT[(kg*4+1)*128 + i] = k4.y;
            kT[(kg*4+2)*128 + i] = k4.z;
            kT[(kg*4+3)*128 + i] = k4.w;
        }
        __syncthreads();

        float acc[8][8];
        #pragma unroll
        for (int a = 0; a < 8; a++)
            #pragma unroll
            for (int b = 0; b < 8; b++) acc[a][b] = 0.f;

        #pragma unroll 2
        for (int k = 0; k < 64; k++){
            float4 a0 = *(const float4*)&qT[k*128 + ty*4];
            float4 a1v = *(const float4*)&qT[k*128 + 64 + ty*4];
            float4 b0 = *(const float4*)&kT[k*128 + tx*4];
            float4 b1 = *(const float4*)&kT[k*128 + 64 + tx*4];
            float av[8] = {a0.x,a0.y,a0.z,a0.w, a1v.x,a1v.y,a1v.z,a1v.w};
            float bv[8] = {b0.x,b0.y,b0.z,b0.w, b1.x,b1.y,b1.z,b1.w};
            #pragma unroll
            for (int a = 0; a < 8; a++)
                #pragma unroll
                for (int b = 0; b < 8; b++)
                    acc[a][b] = fmaf(av[a], bv[b], acc[a][b]);
        }

        float rs[8] = {0,0,0,0,0,0,0,0};
        float cs[8] = {0,0,0,0,0,0,0,0};
        #pragma unroll
        for (int a = 0; a < 8; a++)
            #pragma unroll
            for (int b = 0; b < 8; b++){
                float p = fexp(acc[a][b] * 10.f);
                rs[a] += p; cs[b] += p;
            }

        #pragma unroll
        for (int a = 0; a < 8; a++){
            #pragma unroll
            for (int o = 8; o > 0; o >>= 1)
                rs[a] += __shfl_xor_sync(0xffffffffu, rs[a], o);
        }
        if (tx == 0){
            #pragma unroll
            for (int a = 0; a < 8; a++){
                int row = (a < 4) ? (ty*4 + a) : (64 + ty*4 + a - 4);
                atomicAdd(&g_rowsum[rb2 + row], rs[a]);
            }
        }
        #pragma unroll
        for (int b = 0; b < 4; b++){
            colPart[ty*128 + tx*4 + b]      = cs[b];
            colPart[ty*128 + 64 + tx*4 + b] = cs[b+4];
        }
        __syncthreads();
        if (tid < 128){
            float s = 0.f;
            #pragma unroll
            for (int t = 0; t < 16; t++) s += colPart[t*128 + tid];
            atomicAdd(&g_colsum[cb2 + tid], s);
        }
    }

    gsync(G);

    // ================= PHASE C: final combine (block 0) =================
    if (bid == 0){
        float ms = 0.f;
        for (int blk = quad; blk < 256; blk += 4)
            ms += __ldcg(&g_meanpart[blk*64 + c]);
        sm[tid] = ms;
        __syncthreads();
        if (tid < 64){
            float Mv = sm[tid] + sm[64+tid] + sm[128+tid] + sm[192+tid];
            sm[256 + tid] = Mv*Mv;
        }
        __syncthreads();

        float tv = __ldcg(&g_timepart[tid]);
        float s = 0.f;
        for (int r = tid; r < 2048; r += 256)
            s += logf(__ldcg(&g_rowsum[r])) + logf(__ldcg(&g_colsum[r]))
               - 2.f*__ldcg(&g_diag[r]);
        sm[512 + tid] = tv;
        sm[768 + tid] = s;
        __syncthreads();
        for (int st = 128; st > 0; st >>= 1){
            if (tid < st){
                sm[512+tid] += sm[512+tid+st];
                sm[768+tid] += sm[768+tid+st];
            }
            __syncthreads();
        }
        if (tid == 0){
            float nm2 = 0.f;
            #pragma unroll
            for (int i = 0; i < 64; i++) nm2 += sm[256 + i];
            float normM = sqrtf(nm2);
            float l_con = 0.5f * sm[768] / 2048.f;
            float l_sc  = -normM / 2048.f;
            float l_t   =  sm[512] / 2044.f;
            out[0] = l_con + l_sc + l_t;
            out[1] = l_con;
            out[2] = l_sc;
            out[3] = l_t;
        }
    }
}

// ---------------- launch ----------------
extern "C" void kernel_launch(void* const* d_in, const int* in_sizes, int n_in,
                              void* d_out, int out_size){
    const float* h      = (const float*)d_in[0];
    const float* x_raw  = (const float*)d_in[1];
    const float* W_in   = (const float*)d_in[2];
    const float* b_in   = (const float*)d_in[3];
    const float* dt_emb = (const float*)d_in[4];
    const float* Wm1    = (const float*)d_in[5];
    const float* bm1    = (const float*)d_in[6];
    const float* Wm2    = (const float*)d_in[7];
    const float* bm2    = (const float*)d_in[8];
    const float* Wg     = (const float*)d_in[9];
    const float* a1     = (const float*)d_in[10];
    const float* a2     = (const float*)d_in[11];
    const float* Wf     = (const float*)d_in[12];
    const float* bf     = (const float*)d_in[13];
    float* out = (float*)d_out;

    const int SMEM = SMEMF * 4;
    cudaFuncSetAttribute(fused_kernel, cudaFuncAttributeMaxDynamicSharedMemorySize, SMEM);

    int dev = 0; cudaGetDevice(&dev);
    int sms = 0;
    cudaDeviceGetAttribute(&sms, cudaDevAttrMultiProcessorCount, dev);
    if (sms <= 0) sms = 148;
    int G = sms * 2;
    if (G < 256) G = 256;

    fused_kernel<<<G, 256, SMEM>>>(h, x_raw, W_in, b_in, dt_emb, Wm1, bm1, Wm2, bm2,
                                   Wg, a1, a2, Wf, bf, out);
}